// round 10
// baseline (speedup 1.0000x reference)
#include <cuda_runtime.h>
#include <cuda_bf16.h>
#include <cstdint>

#define NB   16384
#define NE   8
#define DIN  900
#define DM   512
#define DSEL 128
#define EPSF 1e-9f

#define KP     912            // 57 * 16, zero-padded K
#define NK16   57
#define NSTG   4              // cp.async pipeline depth
#define STAGE  24576          // bytes per stage: 4 arrays * 128 rows * 48B
#define AHI    0
#define ALO    6144
#define BHI    12288
#define BLO    18432
#define DYNSM  (NSTG * STAGE) // 98304

#define OUT_GUIDE (NB * DM)
#define OUT_SEL   (NB * DM + 1)

__device__ float g_scratch[(size_t)2 * NB * DM];     // gated per-(token,slot) outputs
__device__ int   g_bucket[NE * NB];
__device__ int   g_count[NE];                        // zero-init at load; combine resets
__device__ float g_gate[2 * NB];
__device__ float g_iw[NB * NE];                      // inactive-mixture weights
__device__ float g_partial[512];
__device__ __nv_bfloat16 g_Xhi[(size_t)NB * KP];
__device__ __nv_bfloat16 g_Xlo[(size_t)NB * KP];
__device__ __nv_bfloat16 g_Whi[(size_t)NE * DM * KP];   // W transposed [e][n][k]
__device__ __nv_bfloat16 g_Wlo[(size_t)NE * DM * KP];

// ---------------------------------------------------------------------------
__device__ __forceinline__ uint32_t smem_u32(const void* p) {
    return (uint32_t)__cvta_generic_to_shared(p);
}
__device__ __forceinline__ void cp16(uint32_t s, const void* g) {
    asm volatile("cp.async.cg.shared.global [%0], [%1], 16;" :: "r"(s), "l"(g));
}
__device__ __forceinline__ void cp_commit() {
    asm volatile("cp.async.commit_group;" ::: "memory");
}
template <int N>
__device__ __forceinline__ void cp_wait() {
    asm volatile("cp.async.wait_group %0;" :: "n"(N) : "memory");
}
__device__ __forceinline__ void ldm_x4(uint32_t* r, uint32_t a) {
    asm volatile("ldmatrix.sync.aligned.m8n8.x4.shared.b16 {%0,%1,%2,%3}, [%4];"
                 : "=r"(r[0]), "=r"(r[1]), "=r"(r[2]), "=r"(r[3]) : "r"(a));
}
#define MMA_BF16(acc, a, b) \
    asm volatile("mma.sync.aligned.m16n8k16.row.col.f32.bf16.bf16.f32 " \
        "{%0,%1,%2,%3}, {%4,%5,%6,%7}, {%8,%9}, {%0,%1,%2,%3};" \
        : "+f"((acc)[0]), "+f"((acc)[1]), "+f"((acc)[2]), "+f"((acc)[3]) \
        : "r"((a)[0]), "r"((a)[1]), "r"((a)[2]), "r"((a)[3]), \
          "r"((b)[0]), "r"((b)[1]))

// ---------------------------------------------------------------------------
// Phase A lite: softmax, gates, top-2, bucketing, guide partials.
__global__ void __launch_bounds__(1024) phaseA_kernel(
    const float* __restrict__ logits,
    const int*   __restrict__ masks)
{
    __shared__ int   lcount[NE];
    __shared__ int   lbase[NE];
    __shared__ int   staging[NE][32];
    __shared__ float warpS[32];

    int tid  = threadIdx.x;
    int warp = tid >> 5;
    int lane = tid & 31;
    if (tid < NE) lcount[tid] = 0;
    __syncthreads();

    int b = blockIdx.x * 32 + warp;

    float raw[NE];
    float mx = -1e30f;
#pragma unroll
    for (int e = 0; e < NE; e++) { raw[e] = logits[b * NE + e]; mx = fmaxf(mx, raw[e]); }
    float sum = 0.f;
#pragma unroll
    for (int e = 0; e < NE; e++) { raw[e] = expf(raw[e] - mx); sum += raw[e]; }
    float inv = 1.f / sum;
    int m[NE];
#pragma unroll
    for (int e = 0; e < NE; e++) { raw[e] *= inv; m[e] = masks[b * NE + e]; }

    float w[NE]; float isum = 0.f;
#pragma unroll
    for (int e = 0; e < NE; e++) { w[e] = (m[e] == 1) ? 0.f : raw[e]; isum += w[e]; }
    float winv = 1.f / (isum + EPSF);

    float a[NE]; float srow = 0.f;
#pragma unroll
    for (int e = 0; e < NE; e++) {
        w[e] *= winv;
        a[e] = (m[e] == 1) ? raw[e] : 0.f;
        srow += a[e];
    }

    float v1 = -1.f, v2 = -1.f; int e1 = 0, e2 = 0;
#pragma unroll
    for (int e = 0; e < NE; e++) {
        if (a[e] > v1) { v2 = v1; e2 = e1; v1 = a[e]; e1 = e; }
        else if (a[e] > v2) { v2 = a[e]; e2 = e; }
    }
    float gs = 1.f / (v1 + v2 + EPSF);
    float g1 = v1 * gs, g2 = v2 * gs;

    if (lane == 0) {
#pragma unroll
        for (int e = 0; e < NE; e++) g_iw[b * NE + e] = w[e];
        g_gate[2 * b]     = g1;
        g_gate[2 * b + 1] = g2;
        if (g1 > 0.f) { int p = atomicAdd(&lcount[e1], 1); staging[e1][p] = 2 * b; }
        if (g2 > 0.f) { int p = atomicAdd(&lcount[e2], 1); staging[e2][p] = 2 * b + 1; }
        warpS[warp] = srow;
    }
    __syncthreads();
    if (tid < NE) lbase[tid] = atomicAdd(&g_count[tid], lcount[tid]);
    if (tid == 0) {
        float s = 0.f;
        for (int i = 0; i < 32; i++) s += warpS[i];
        g_partial[blockIdx.x] = s;
    }
    __syncthreads();
#pragma unroll
    for (int e = 0; e < NE; e++) {
        for (int i = tid; i < lcount[e]; i += blockDim.x)
            g_bucket[e * NB + lbase[e] + i] = staging[e][i];
    }
}

// ---------------------------------------------------------------------------
// Split X into bf16 hi/lo, pad K to 912 with zeros.
__global__ void split_x_kernel(const float* __restrict__ X) {
    size_t i = (size_t)blockIdx.x * blockDim.x + threadIdx.x;
    if (i >= (size_t)NB * KP) return;
    int b = (int)(i / KP), k = (int)(i % KP);
    float v = (k < DIN) ? X[(size_t)b * DIN + k] : 0.f;
    __nv_bfloat16 h = __float2bfloat16(v);
    g_Xhi[i] = h;
    g_Xlo[i] = __float2bfloat16(v - __bfloat162float(h));
}

// ---------------------------------------------------------------------------
// Transpose + split W[e][k][n] -> [e][n][kpad] bf16 hi/lo.
__global__ void split_w_kernel(const float* __restrict__ W) {
    __shared__ float tile[32][33];
    int e = blockIdx.z;
    int k0 = blockIdx.x * 32;
    int n0 = blockIdx.y * 32;
    int tx = threadIdx.x, ty = threadIdx.y;
#pragma unroll
    for (int i = 0; i < 4; i++) {
        int k = k0 + ty + i * 8;
        tile[ty + i * 8][tx] = (k < DIN) ? W[((size_t)e * DIN + k) * DM + n0 + tx] : 0.f;
    }
    __syncthreads();
#pragma unroll
    for (int i = 0; i < 4; i++) {
        int n = n0 + ty + i * 8;
        int kk = k0 + tx;
        if (kk < KP) {
            float v = tile[tx][ty + i * 8];
            __nv_bfloat16 h = __float2bfloat16(v);
            size_t idx = ((size_t)e * DM + n) * KP + kk;
            g_Whi[idx] = h;
            g_Wlo[idx] = __float2bfloat16(v - __bfloat162float(h));
        }
    }
}

// ---------------------------------------------------------------------------
// Tensor-core grouped GEMM: mma.sync bf16, 3-pass hi/lo split.  (R7 core)
// CTA tile 128x128, BK=16, 4-stage cp.async pipeline, 8 warps (2m x 4n),
// 2 CTAs/SM, one barrier per k-step, pass-major MMA issue.
extern __shared__ char sm_dyn[];

__global__ void __launch_bounds__(256, 2) gemm_kernel(
    const float* __restrict__ bias)
{
    int e   = blockIdx.z;
    int cnt = g_count[e];
    int rt0 = blockIdx.x * 128;
    if (rt0 >= cnt) return;
    int rows = cnt - rt0; if (rows > 128) rows = 128;
    int n0 = blockIdx.y * 128;

    __shared__ int   sEntry[128];
    __shared__ float sGate[128];
    __shared__ float sBias[128];

    int t = threadIdx.x;
    int wid = t >> 5, lane = t & 31;
    int wm = wid & 1, wn = wid >> 1;       // 2 x 4 warp grid

    if (t < 128) {
        int entry = 0; float g = 0.f;
        if (t < rows) { entry = g_bucket[e * NB + rt0 + t]; g = g_gate[entry]; }
        sEntry[t] = entry; sGate[t] = g;
        sBias[t]  = bias[e * DM + n0 + t];
    }
    __syncthreads();

    uint32_t dynb = smem_u32(sm_dyn);

    // per-thread cp.async sources: row = t>>1, chunk = t&1 (16B each)
    int lrow = t >> 1, lch = t & 1;
    const __nv_bfloat16* aHiSrc =
        g_Xhi + (size_t)(sEntry[lrow] >> 1) * KP + lch * 8;
    const __nv_bfloat16* aLoSrc =
        g_Xlo + (size_t)(sEntry[lrow] >> 1) * KP + lch * 8;
    const __nv_bfloat16* bHiSrc =
        g_Whi + ((size_t)e * DM + n0 + lrow) * KP + lch * 8;
    const __nv_bfloat16* bLoSrc =
        g_Wlo + ((size_t)e * DM + n0 + lrow) * KP + lch * 8;
    uint32_t smoff = lrow * 48 + lch * 16;

    // prologue: stages 0..NSTG-2
#pragma unroll
    for (int s = 0; s < NSTG - 1; s++) {
        uint32_t sb = dynb + s * STAGE;
        cp16(sb + AHI + smoff, aHiSrc + s * 16);
        cp16(sb + ALO + smoff, aLoSrc + s * 16);
        cp16(sb + BHI + smoff, bHiSrc + s * 16);
        cp16(sb + BLO + smoff, bLoSrc + s * 16);
        cp_commit();
    }

    float acc[4][4][4];
#pragma unroll
    for (int i = 0; i < 4; i++)
#pragma unroll
        for (int j = 0; j < 4; j++)
#pragma unroll
            for (int q = 0; q < 4; q++) acc[i][j][q] = 0.f;

    // fragment address offsets
    int l7 = lane & 7;
    uint32_t aRowOff = (uint32_t)((wm * 64 + l7 + ((lane >> 3) & 1) * 8) * 48
                                  + ((lane >> 4) & 1) * 16);
    // B via ldm_x4: one x4 gives two adjacent tn fragments (8+8 cols)
    uint32_t bRow4Off = (uint32_t)((wn * 32 + ((lane >> 4) & 1) * 8 + l7) * 48
                                   + ((lane >> 3) & 1) * 16);

    for (int ks = 0; ks < NK16; ks++) {
        cp_wait<NSTG - 2>();
        __syncthreads();   // single barrier per k-step

        int ns = ks + NSTG - 1;
        if (ns < NK16) {
            uint32_t nb = dynb + (ns % NSTG) * STAGE;
            cp16(nb + AHI + smoff, aHiSrc + ns * 16);
            cp16(nb + ALO + smoff, aLoSrc + ns * 16);
            cp16(nb + BHI + smoff, bHiSrc + ns * 16);
            cp16(nb + BLO + smoff, bLoSrc + ns * 16);
        }
        cp_commit();

        uint32_t sb = dynb + (ks % NSTG) * STAGE;

        // B fragments: 4 ldm_x4 (hi/lo x two tn-pairs)
        uint32_t bh[4][2], blo[4][2];
#pragma unroll
        for (int p = 0; p < 2; p++) {
            uint32_t r4[4];
            uint32_t ba = sb + BHI + bRow4Off + p * 16 * 48;
            ldm_x4(r4, ba);
            bh[2 * p][0] = r4[0]; bh[2 * p][1] = r4[1];
            bh[2 * p + 1][0] = r4[2]; bh[2 * p + 1][1] = r4[3];
            ldm_x4(r4, ba + (BLO - BHI));
            blo[2 * p][0] = r4[0]; blo[2 * p][1] = r4[1];
            blo[2 * p + 1][0] = r4[2]; blo[2 * p + 1][1] = r4[3];
        }

        // A fragments: double-buffered across tm
        uint32_t ah[2][4], al[2][4];
        {
            uint32_t aa = sb + AHI + aRowOff;
            ldm_x4(ah[0], aa);
            ldm_x4(al[0], aa + (ALO - AHI));
        }
#pragma unroll
        for (int tm = 0; tm < 4; tm++) {
            int cur = tm & 1;
            if (tm < 3) {
                uint32_t aa = sb + AHI + aRowOff + (tm + 1) * 16 * 48;
                ldm_x4(ah[cur ^ 1], aa);
                ldm_x4(al[cur ^ 1], aa + (ALO - AHI));
            }
            // pass-major issue: consecutive MMAs -> independent accumulators
#pragma unroll
            for (int tn = 0; tn < 4; tn++)
                MMA_BF16(acc[tm][tn], ah[cur], bh[tn]);
#pragma unroll
            for (int tn = 0; tn < 4; tn++)
                MMA_BF16(acc[tm][tn], ah[cur], blo[tn]);
#pragma unroll
            for (int tn = 0; tn < 4; tn++)
                MMA_BF16(acc[tm][tn], al[cur], bh[tn]);
        }
    }

    // epilogue: bias + gate, write to scratch
    int rq = lane >> 2, cq = (lane & 3) * 2;
#pragma unroll
    for (int tm = 0; tm < 4; tm++) {
        int r0 = wm * 64 + tm * 16 + rq;
        int r1 = r0 + 8;
#pragma unroll
        for (int tn = 0; tn < 4; tn++) {
            int cl = wn * 32 + tn * 8 + cq;
            float b0 = sBias[cl], b1 = sBias[cl + 1];
            if (r0 < rows) {
                float g = sGate[r0];
                float2 o = make_float2(g * (acc[tm][tn][0] + b0),
                                       g * (acc[tm][tn][1] + b1));
                *(float2*)(g_scratch + (size_t)sEntry[r0] * DM + n0 + cl) = o;
            }
            if (r1 < rows) {
                float g = sGate[r1];
                float2 o = make_float2(g * (acc[tm][tn][2] + b0),
                                       g * (acc[tm][tn][3] + b1));
                *(float2*)(g_scratch + (size_t)sEntry[r1] * DM + n0 + cl) = o;
            }
        }
    }
}

// ---------------------------------------------------------------------------
__global__ void guide_kernel(float* __restrict__ out) {
    __shared__ float sm[512];
    int t = threadIdx.x;
    sm[t] = g_partial[t];
    __syncthreads();
    for (int s = 256; s > 0; s >>= 1) {
        if (t < s) sm[t] += sm[t + s];
        __syncthreads();
    }
    if (t == 0) {
        float sv = sm[0] / (float)NB;
        float d = 1.f - sv;
        out[OUT_GUIDE] = d * d;
    }
}

// ---------------------------------------------------------------------------
// Streaming selection-embedding: out_sel[b, s] = sum_e iw[b,e]*selemb[b,e,s].
__global__ void __launch_bounds__(256) selemb_kernel(
    const float* __restrict__ selemb,
    float*       __restrict__ out)
{
    int warp = (blockIdx.x * 256 + threadIdx.x) >> 5;
    int lane = threadIdx.x & 31;
    int b = warp;

    float w[NE];
#pragma unroll
    for (int e = 0; e < NE; e++) w[e] = g_iw[b * NE + e];

    const float4* base = (const float4*)(selemb + (size_t)b * NE * DSEL);
    float4 acc = make_float4(0.f, 0.f, 0.f, 0.f);
#pragma unroll
    for (int e = 0; e < NE; e++) {
        float4 v = base[e * (DSEL / 4) + lane];
        acc.x += w[e] * v.x; acc.y += w[e] * v.y;
        acc.z += w[e] * v.z; acc.w += w[e] * v.w;
    }
    float* dst = out + OUT_SEL + (size_t)b * DSEL + lane * 4;
    dst[0] = acc.x; dst[1] = acc.y; dst[2] = acc.z; dst[3] = acc.w;
}

// ---------------------------------------------------------------------------
// Combine slot0 + slot1, quantize to bf16, write f32. Also resets g_count
// for the next graph replay (runs after gemm consumed the counts).
__global__ void combine_kernel(float* __restrict__ out) {
    int idx = blockIdx.x * blockDim.x + threadIdx.x;
    if (blockIdx.x == 0 && threadIdx.x < NE) g_count[threadIdx.x] = 0;
    int b   = idx >> 7;
    int m4  = (idx & 127) << 2;
    float g1 = g_gate[2 * b], g2 = g_gate[2 * b + 1];
    float4 v = make_float4(0.f, 0.f, 0.f, 0.f);
    if (g1 > 0.f) {
        float4 s = *(const float4*)(g_scratch + (size_t)(2 * b) * DM + m4);
        v.x += s.x; v.y += s.y; v.z += s.z; v.w += s.w;
    }
    if (g2 > 0.f) {
        float4 s = *(const float4*)(g_scratch + (size_t)(2 * b + 1) * DM + m4);
        v.x += s.x; v.y += s.y; v.z += s.z; v.w += s.w;
    }
    float4 o;
    o.x = __bfloat162float(__float2bfloat16(v.x));
    o.y = __bfloat162float(__float2bfloat16(v.y));
    o.z = __bfloat162float(__float2bfloat16(v.z));
    o.w = __bfloat162float(__float2bfloat16(v.w));
    ((float4*)out)[idx] = o;
}

// ---------------------------------------------------------------------------
extern "C" void kernel_launch(void* const* d_in, const int* in_sizes, int n_in,
                              void* d_out, int out_size)
{
    const float* X      = (const float*)d_in[0];
    const float* logits = (const float*)d_in[1];
    const int*   masks  = (const int*)  d_in[2];
    const float* selemb = (const float*)d_in[3];
    const float* W      = (const float*)d_in[4];
    const float* bias   = (const float*)d_in[5];
    float* out = (float*)d_out;

    cudaFuncSetAttribute(gemm_kernel,
                         cudaFuncAttributeMaxDynamicSharedMemorySize, DYNSM);

    phaseA_kernel<<<NB / 32, 1024>>>(logits, masks);                       // 1
    split_x_kernel<<<(int)(((size_t)NB * KP + 255) / 256), 256>>>(X);      // 2
    dim3 wg((KP + 31) / 32, DM / 32, NE);
    split_w_kernel<<<wg, dim3(32, 8)>>>(W);                                // 3
    dim3 g(NB / 128, DM / 128, NE);
    gemm_kernel<<<g, 256, DYNSM>>>(bias);                                  // 4 (profiled)
    guide_kernel<<<1, 512>>>(out);                                         // 5
    selemb_kernel<<<NB / 8, 256>>>(selemb, out);                           // 6
    combine_kernel<<<(NB * DM / 4) / 256, 256>>>(out);                     // 7
}

// round 11
// speedup vs baseline: 1.0218x; 1.0218x over previous
#include <cuda_runtime.h>
#include <cuda_bf16.h>
#include <cstdint>

#define NB   16384
#define NE   8
#define DIN  900
#define DM   512
#define DSEL 128
#define EPSF 1e-9f

#define KP     928            // 58 * 16, zero-padded K
#define NSUP   29             // super k-steps of K=32
#define NSTG   3              // super-stage pipeline depth
#define SSTAGE 32768          // bytes per super-stage (2 subs x 4 arrays x 128 x 32B)
#define SUB    16384          // bytes per 16-K sub-block
#define AHI    0
#define ALO    4096
#define BHI    8192
#define BLO    12288
#define DYNSM  (NSTG * SSTAGE) // 98304

#define OUT_GUIDE (NB * DM)
#define OUT_SEL   (NB * DM + 1)

__device__ float g_scratch[(size_t)2 * NB * DM];     // gated per-(token,slot) outputs
__device__ int   g_bucket[NE * NB];
__device__ int   g_count[NE];                        // zero-init at load; combine resets
__device__ float g_gate[2 * NB];
__device__ float g_iw[NB * NE];                      // inactive-mixture weights
__device__ float g_partial[512];
__device__ __nv_bfloat16 g_Xhi[(size_t)NB * KP];
__device__ __nv_bfloat16 g_Xlo[(size_t)NB * KP];
__device__ __nv_bfloat16 g_Whi[(size_t)NE * DM * KP];   // W transposed [e][n][k]
__device__ __nv_bfloat16 g_Wlo[(size_t)NE * DM * KP];

// ---------------------------------------------------------------------------
__device__ __forceinline__ uint32_t smem_u32(const void* p) {
    return (uint32_t)__cvta_generic_to_shared(p);
}
__device__ __forceinline__ void cp16(uint32_t s, const void* g) {
    asm volatile("cp.async.cg.shared.global [%0], [%1], 16;" :: "r"(s), "l"(g));
}
__device__ __forceinline__ void cp_commit() {
    asm volatile("cp.async.commit_group;" ::: "memory");
}
template <int N>
__device__ __forceinline__ void cp_wait() {
    asm volatile("cp.async.wait_group %0;" :: "n"(N) : "memory");
}
__device__ __forceinline__ void ldm_x4(uint32_t* r, uint32_t a) {
    asm volatile("ldmatrix.sync.aligned.m8n8.x4.shared.b16 {%0,%1,%2,%3}, [%4];"
                 : "=r"(r[0]), "=r"(r[1]), "=r"(r[2]), "=r"(r[3]) : "r"(a));
}
#define MMA_BF16(acc, a, b) \
    asm volatile("mma.sync.aligned.m16n8k16.row.col.f32.bf16.bf16.f32 " \
        "{%0,%1,%2,%3}, {%4,%5,%6,%7}, {%8,%9}, {%0,%1,%2,%3};" \
        : "+f"((acc)[0]), "+f"((acc)[1]), "+f"((acc)[2]), "+f"((acc)[3]) \
        : "r"((a)[0]), "r"((a)[1]), "r"((a)[2]), "r"((a)[3]), \
          "r"((b)[0]), "r"((b)[1]))

// ---------------------------------------------------------------------------
// Phase A lite: softmax, gates, top-2, bucketing, guide partials.
__global__ void __launch_bounds__(1024) phaseA_kernel(
    const float* __restrict__ logits,
    const int*   __restrict__ masks)
{
    __shared__ int   lcount[NE];
    __shared__ int   lbase[NE];
    __shared__ int   staging[NE][32];
    __shared__ float warpS[32];

    int tid  = threadIdx.x;
    int warp = tid >> 5;
    int lane = tid & 31;
    if (tid < NE) lcount[tid] = 0;
    __syncthreads();

    int b = blockIdx.x * 32 + warp;

    float raw[NE];
    float mx = -1e30f;
#pragma unroll
    for (int e = 0; e < NE; e++) { raw[e] = logits[b * NE + e]; mx = fmaxf(mx, raw[e]); }
    float sum = 0.f;
#pragma unroll
    for (int e = 0; e < NE; e++) { raw[e] = expf(raw[e] - mx); sum += raw[e]; }
    float inv = 1.f / sum;
    int m[NE];
#pragma unroll
    for (int e = 0; e < NE; e++) { raw[e] *= inv; m[e] = masks[b * NE + e]; }

    float w[NE]; float isum = 0.f;
#pragma unroll
    for (int e = 0; e < NE; e++) { w[e] = (m[e] == 1) ? 0.f : raw[e]; isum += w[e]; }
    float winv = 1.f / (isum + EPSF);

    float a[NE]; float srow = 0.f;
#pragma unroll
    for (int e = 0; e < NE; e++) {
        w[e] *= winv;
        a[e] = (m[e] == 1) ? raw[e] : 0.f;
        srow += a[e];
    }

    float v1 = -1.f, v2 = -1.f; int e1 = 0, e2 = 0;
#pragma unroll
    for (int e = 0; e < NE; e++) {
        if (a[e] > v1) { v2 = v1; e2 = e1; v1 = a[e]; e1 = e; }
        else if (a[e] > v2) { v2 = a[e]; e2 = e; }
    }
    float gs = 1.f / (v1 + v2 + EPSF);
    float g1 = v1 * gs, g2 = v2 * gs;

    if (lane == 0) {
#pragma unroll
        for (int e = 0; e < NE; e++) g_iw[b * NE + e] = w[e];
        g_gate[2 * b]     = g1;
        g_gate[2 * b + 1] = g2;
        if (g1 > 0.f) { int p = atomicAdd(&lcount[e1], 1); staging[e1][p] = 2 * b; }
        if (g2 > 0.f) { int p = atomicAdd(&lcount[e2], 1); staging[e2][p] = 2 * b + 1; }
        warpS[warp] = srow;
    }
    __syncthreads();
    if (tid < NE) lbase[tid] = atomicAdd(&g_count[tid], lcount[tid]);
    if (tid == 0) {
        float s = 0.f;
        for (int i = 0; i < 32; i++) s += warpS[i];
        g_partial[blockIdx.x] = s;
    }
    __syncthreads();
#pragma unroll
    for (int e = 0; e < NE; e++) {
        for (int i = tid; i < lcount[e]; i += blockDim.x)
            g_bucket[e * NB + lbase[e] + i] = staging[e][i];
    }
}

// ---------------------------------------------------------------------------
// Split X into bf16 hi/lo, pad K to 928 with zeros.
__global__ void split_x_kernel(const float* __restrict__ X) {
    size_t i = (size_t)blockIdx.x * blockDim.x + threadIdx.x;
    if (i >= (size_t)NB * KP) return;
    int b = (int)(i / KP), k = (int)(i % KP);
    float v = (k < DIN) ? X[(size_t)b * DIN + k] : 0.f;
    __nv_bfloat16 h = __float2bfloat16(v);
    g_Xhi[i] = h;
    g_Xlo[i] = __float2bfloat16(v - __bfloat162float(h));
}

// ---------------------------------------------------------------------------
// Transpose + split W[e][k][n] -> [e][n][kpad] bf16 hi/lo.
__global__ void split_w_kernel(const float* __restrict__ W) {
    __shared__ float tile[32][33];
    int e = blockIdx.z;
    int k0 = blockIdx.x * 32;
    int n0 = blockIdx.y * 32;
    int tx = threadIdx.x, ty = threadIdx.y;
#pragma unroll
    for (int i = 0; i < 4; i++) {
        int k = k0 + ty + i * 8;
        tile[ty + i * 8][tx] = (k < DIN) ? W[((size_t)e * DIN + k) * DM + n0 + tx] : 0.f;
    }
    __syncthreads();
#pragma unroll
    for (int i = 0; i < 4; i++) {
        int n = n0 + ty + i * 8;
        int kk = k0 + tx;
        if (kk < KP) {
            float v = tile[tx][ty + i * 8];
            __nv_bfloat16 h = __float2bfloat16(v);
            size_t idx = ((size_t)e * DM + n) * KP + kk;
            g_Whi[idx] = h;
            g_Wlo[idx] = __float2bfloat16(v - __bfloat162float(h));
        }
    }
}

// ---------------------------------------------------------------------------
// Tensor-core grouped GEMM: mma.sync bf16, 3-pass hi/lo split.
// CTA tile 128x128, super-stage BK=32 (2 x 16-K sub-blocks), 3-stage pipeline,
// ONE cp_wait + ONE barrier per 32-K (29 sync events vs 57). Dense 32B rows
// (2-way LDSM conflict accepted; LDSM has >=4x headroom). 8 warps, 2 CTAs/SM.
extern __shared__ char sm_dyn[];

__global__ void __launch_bounds__(256, 2) gemm_kernel(
    const float* __restrict__ bias)
{
    int e   = blockIdx.z;
    int cnt = g_count[e];
    int rt0 = blockIdx.x * 128;
    if (rt0 >= cnt) return;
    int rows = cnt - rt0; if (rows > 128) rows = 128;
    int n0 = blockIdx.y * 128;

    __shared__ int   sEntry[128];
    __shared__ float sGate[128];
    __shared__ float sBias[128];

    int t = threadIdx.x;
    int wid = t >> 5, lane = t & 31;
    int wm = wid & 1, wn = wid >> 1;       // 2 x 4 warp grid

    if (t < 128) {
        int entry = 0; float g = 0.f;
        if (t < rows) { entry = g_bucket[e * NB + rt0 + t]; g = g_gate[entry]; }
        sEntry[t] = entry; sGate[t] = g;
        sBias[t]  = bias[e * DM + n0 + t];
    }
    __syncthreads();

    uint32_t dynb = smem_u32(sm_dyn);

    // per-thread cp.async sources: row = t>>1, chunk = t&1 (16B each)
    int lrow = t >> 1, lch = t & 1;
    const __nv_bfloat16* aHiSrc =
        g_Xhi + (size_t)(sEntry[lrow] >> 1) * KP + lch * 8;
    const __nv_bfloat16* aLoSrc =
        g_Xlo + (size_t)(sEntry[lrow] >> 1) * KP + lch * 8;
    const __nv_bfloat16* bHiSrc =
        g_Whi + ((size_t)e * DM + n0 + lrow) * KP + lch * 8;
    const __nv_bfloat16* bLoSrc =
        g_Wlo + ((size_t)e * DM + n0 + lrow) * KP + lch * 8;
    uint32_t smoff = lrow * 32 + lch * 16;

    // issue one super-stage (2 sub-blocks, 8 cp16 per thread)
    auto issue_super = [&](int sup) {
        uint32_t sb = dynb + (sup % NSTG) * SSTAGE;
#pragma unroll
        for (int s = 0; s < 2; s++) {
            uint32_t ssb = sb + s * SUB;
            int ko = sup * 32 + s * 16;
            cp16(ssb + AHI + smoff, aHiSrc + ko);
            cp16(ssb + ALO + smoff, aLoSrc + ko);
            cp16(ssb + BHI + smoff, bHiSrc + ko);
            cp16(ssb + BLO + smoff, bLoSrc + ko);
        }
    };

    // prologue: supers 0 and 1 (one commit group each)
    issue_super(0); cp_commit();
    issue_super(1); cp_commit();

    float acc[4][4][4];
#pragma unroll
    for (int i = 0; i < 4; i++)
#pragma unroll
        for (int j = 0; j < 4; j++)
#pragma unroll
            for (int q = 0; q < 4; q++) acc[i][j][q] = 0.f;

    // fragment address offsets (32B row stride)
    int l7 = lane & 7;
    uint32_t aRowOff = (uint32_t)((wm * 64 + l7 + ((lane >> 3) & 1) * 8) * 32
                                  + ((lane >> 4) & 1) * 16);
    uint32_t bRow4Off = (uint32_t)((wn * 32 + ((lane >> 4) & 1) * 8 + l7) * 32
                                   + ((lane >> 3) & 1) * 16);

    for (int i = 0; i < NSUP; i++) {
        cp_wait<1>();       // own group for super i done (newest may pend)
        __syncthreads();    // publish super i; all warps done reading super i-1

        // refill the stage freed at iter i-1 (safe: all warps past barrier)
        if (i + 2 < NSUP) issue_super(i + 2);
        cp_commit();

        uint32_t sb = dynb + (i % NSTG) * SSTAGE;
#pragma unroll
        for (int s = 0; s < 2; s++) {
            uint32_t ssb = sb + s * SUB;

            // B fragments: 4 ldm_x4 (hi/lo x two tn-pairs)
            uint32_t bh[4][2], blo[4][2];
#pragma unroll
            for (int p = 0; p < 2; p++) {
                uint32_t r4[4];
                uint32_t ba = ssb + BHI + bRow4Off + p * 16 * 32;
                ldm_x4(r4, ba);
                bh[2 * p][0] = r4[0]; bh[2 * p][1] = r4[1];
                bh[2 * p + 1][0] = r4[2]; bh[2 * p + 1][1] = r4[3];
                ldm_x4(r4, ba + (BLO - BHI));
                blo[2 * p][0] = r4[0]; blo[2 * p][1] = r4[1];
                blo[2 * p + 1][0] = r4[2]; blo[2 * p + 1][1] = r4[3];
            }

            // A fragments: double-buffered across tm
            uint32_t ah[2][4], al[2][4];
            {
                uint32_t aa = ssb + AHI + aRowOff;
                ldm_x4(ah[0], aa);
                ldm_x4(al[0], aa + (ALO - AHI));
            }
#pragma unroll
            for (int tm = 0; tm < 4; tm++) {
                int cur = tm & 1;
                if (tm < 3) {
                    uint32_t aa = ssb + AHI + aRowOff + (tm + 1) * 16 * 32;
                    ldm_x4(ah[cur ^ 1], aa);
                    ldm_x4(al[cur ^ 1], aa + (ALO - AHI));
                }
                // pass-major issue: consecutive MMAs -> independent accumulators
#pragma unroll
                for (int tn = 0; tn < 4; tn++)
                    MMA_BF16(acc[tm][tn], ah[cur], bh[tn]);
#pragma unroll
                for (int tn = 0; tn < 4; tn++)
                    MMA_BF16(acc[tm][tn], ah[cur], blo[tn]);
#pragma unroll
                for (int tn = 0; tn < 4; tn++)
                    MMA_BF16(acc[tm][tn], al[cur], bh[tn]);
            }
        }
    }

    // epilogue: bias + gate, write to scratch
    int rq = lane >> 2, cq = (lane & 3) * 2;
#pragma unroll
    for (int tm = 0; tm < 4; tm++) {
        int r0 = wm * 64 + tm * 16 + rq;
        int r1 = r0 + 8;
#pragma unroll
        for (int tn = 0; tn < 4; tn++) {
            int cl = wn * 32 + tn * 8 + cq;
            float b0 = sBias[cl], b1 = sBias[cl + 1];
            if (r0 < rows) {
                float g = sGate[r0];
                float2 o = make_float2(g * (acc[tm][tn][0] + b0),
                                       g * (acc[tm][tn][1] + b1));
                *(float2*)(g_scratch + (size_t)sEntry[r0] * DM + n0 + cl) = o;
            }
            if (r1 < rows) {
                float g = sGate[r1];
                float2 o = make_float2(g * (acc[tm][tn][2] + b0),
                                       g * (acc[tm][tn][3] + b1));
                *(float2*)(g_scratch + (size_t)sEntry[r1] * DM + n0 + cl) = o;
            }
        }
    }
}

// ---------------------------------------------------------------------------
__global__ void guide_kernel(float* __restrict__ out) {
    __shared__ float sm[512];
    int t = threadIdx.x;
    sm[t] = g_partial[t];
    __syncthreads();
    for (int s = 256; s > 0; s >>= 1) {
        if (t < s) sm[t] += sm[t + s];
        __syncthreads();
    }
    if (t == 0) {
        float sv = sm[0] / (float)NB;
        float d = 1.f - sv;
        out[OUT_GUIDE] = d * d;
    }
}

// ---------------------------------------------------------------------------
// Streaming selection-embedding: out_sel[b, s] = sum_e iw[b,e]*selemb[b,e,s].
__global__ void __launch_bounds__(256) selemb_kernel(
    const float* __restrict__ selemb,
    float*       __restrict__ out)
{
    int warp = (blockIdx.x * 256 + threadIdx.x) >> 5;
    int lane = threadIdx.x & 31;
    int b = warp;

    float w[NE];
#pragma unroll
    for (int e = 0; e < NE; e++) w[e] = g_iw[b * NE + e];

    const float4* base = (const float4*)(selemb + (size_t)b * NE * DSEL);
    float4 acc = make_float4(0.f, 0.f, 0.f, 0.f);
#pragma unroll
    for (int e = 0; e < NE; e++) {
        float4 v = base[e * (DSEL / 4) + lane];
        acc.x += w[e] * v.x; acc.y += w[e] * v.y;
        acc.z += w[e] * v.z; acc.w += w[e] * v.w;
    }
    float* dst = out + OUT_SEL + (size_t)b * DSEL + lane * 4;
    dst[0] = acc.x; dst[1] = acc.y; dst[2] = acc.z; dst[3] = acc.w;
}

// ---------------------------------------------------------------------------
// Combine slot0 + slot1, quantize to bf16, write f32. Also resets g_count
// for the next graph replay (runs after gemm consumed the counts).
__global__ void combine_kernel(float* __restrict__ out) {
    int idx = blockIdx.x * blockDim.x + threadIdx.x;
    if (blockIdx.x == 0 && threadIdx.x < NE) g_count[threadIdx.x] = 0;
    int b   = idx >> 7;
    int m4  = (idx & 127) << 2;
    float g1 = g_gate[2 * b], g2 = g_gate[2 * b + 1];
    float4 v = make_float4(0.f, 0.f, 0.f, 0.f);
    if (g1 > 0.f) {
        float4 s = *(const float4*)(g_scratch + (size_t)(2 * b) * DM + m4);
        v.x += s.x; v.y += s.y; v.z += s.z; v.w += s.w;
    }
    if (g2 > 0.f) {
        float4 s = *(const float4*)(g_scratch + (size_t)(2 * b + 1) * DM + m4);
        v.x += s.x; v.y += s.y; v.z += s.z; v.w += s.w;
    }
    float4 o;
    o.x = __bfloat162float(__float2bfloat16(v.x));
    o.y = __bfloat162float(__float2bfloat16(v.y));
    o.z = __bfloat162float(__float2bfloat16(v.z));
    o.w = __bfloat162float(__float2bfloat16(v.w));
    ((float4*)out)[idx] = o;
}

// ---------------------------------------------------------------------------
extern "C" void kernel_launch(void* const* d_in, const int* in_sizes, int n_in,
                              void* d_out, int out_size)
{
    const float* X      = (const float*)d_in[0];
    const float* logits = (const float*)d_in[1];
    const int*   masks  = (const int*)  d_in[2];
    const float* selemb = (const float*)d_in[3];
    const float* W      = (const float*)d_in[4];
    const float* bias   = (const float*)d_in[5];
    float* out = (float*)d_out;

    cudaFuncSetAttribute(gemm_kernel,
                         cudaFuncAttributeMaxDynamicSharedMemorySize, DYNSM);

    phaseA_kernel<<<NB / 32, 1024>>>(logits, masks);                       // 1
    split_x_kernel<<<(int)(((size_t)NB * KP + 255) / 256), 256>>>(X);      // 2
    dim3 wg(KP / 32, DM / 32, NE);
    split_w_kernel<<<wg, dim3(32, 8)>>>(W);                                // 3
    dim3 g(NB / 128, DM / 128, NE);
    gemm_kernel<<<g, 256, DYNSM>>>(bias);                                  // 4 (profiled)
    guide_kernel<<<1, 512>>>(out);                                         // 5
    selemb_kernel<<<NB / 8, 256>>>(selemb, out);                           // 6
    combine_kernel<<<(NB * DM / 4) / 256, 256>>>(out);                     // 7
}

// round 12
// speedup vs baseline: 1.0771x; 1.0541x over previous
#include <cuda_runtime.h>
#include <cuda_bf16.h>
#include <cstdint>

#define NB   16384
#define NE   8
#define DIN  900
#define DM   512
#define DSEL 128
#define EPSF 1e-9f

#define KP     928            // 58 * 16, zero-padded K
#define NSUP   29             // super k-steps of K=32
#define NSTG   3              // super-stage pipeline depth
#define SSTAGE 32768          // bytes per super-stage (2 subs x 4 arrays x 128 x 32B)
#define SUB    16384          // bytes per 16-K sub-block
#define AHI    0
#define ALO    4096
#define BHI    8192
#define BLO    12288
#define DYNSM  (NSTG * SSTAGE) // 98304

#define OUT_GUIDE (NB * DM)
#define OUT_SEL   (NB * DM + 1)

__device__ float g_scratch[(size_t)2 * NB * DM];     // gated per-(token,slot) outputs
__device__ int   g_bucket[NE * NB];
__device__ int   g_count[NE];                        // zero-init at load; combine resets
__device__ float g_gate[2 * NB];
__device__ float g_iw[NB * NE];                      // inactive-mixture weights
__device__ float g_partial[512];
__device__ __nv_bfloat16 g_Xhi[(size_t)NB * KP];
__device__ __nv_bfloat16 g_Xlo[(size_t)NB * KP];
__device__ __nv_bfloat16 g_Whi[(size_t)NE * DM * KP];   // W transposed [e][n][k]
__device__ __nv_bfloat16 g_Wlo[(size_t)NE * DM * KP];

// ---------------------------------------------------------------------------
__device__ __forceinline__ uint32_t smem_u32(const void* p) {
    return (uint32_t)__cvta_generic_to_shared(p);
}
__device__ __forceinline__ void cp16(uint32_t s, const void* g) {
    asm volatile("cp.async.cg.shared.global [%0], [%1], 16;" :: "r"(s), "l"(g));
}
__device__ __forceinline__ void cp_commit() {
    asm volatile("cp.async.commit_group;" ::: "memory");
}
template <int N>
__device__ __forceinline__ void cp_wait() {
    asm volatile("cp.async.wait_group %0;" :: "n"(N) : "memory");
}
__device__ __forceinline__ void ldm_x4(uint32_t* r, uint32_t a) {
    asm volatile("ldmatrix.sync.aligned.m8n8.x4.shared.b16 {%0,%1,%2,%3}, [%4];"
                 : "=r"(r[0]), "=r"(r[1]), "=r"(r[2]), "=r"(r[3]) : "r"(a));
}
#define MMA_BF16(acc, a, b) \
    asm volatile("mma.sync.aligned.m16n8k16.row.col.f32.bf16.bf16.f32 " \
        "{%0,%1,%2,%3}, {%4,%5,%6,%7}, {%8,%9}, {%0,%1,%2,%3};" \
        : "+f"((acc)[0]), "+f"((acc)[1]), "+f"((acc)[2]), "+f"((acc)[3]) \
        : "r"((a)[0]), "r"((a)[1]), "r"((a)[2]), "r"((a)[3]), \
          "r"((b)[0]), "r"((b)[1]))

// swizzled offset for (row, chunk16) in a 128x32B array: kills LDSM conflicts
__device__ __forceinline__ uint32_t swz(int row, int chunk) {
    return (uint32_t)(row * 32 + (chunk ^ ((row >> 2) & 1)) * 16);
}

// ---------------------------------------------------------------------------
// Phase A lite: softmax, gates, top-2, bucketing, guide partials.
__global__ void __launch_bounds__(1024) phaseA_kernel(
    const float* __restrict__ logits,
    const int*   __restrict__ masks)
{
    __shared__ int   lcount[NE];
    __shared__ int   lbase[NE];
    __shared__ int   staging[NE][32];
    __shared__ float warpS[32];

    int tid  = threadIdx.x;
    int warp = tid >> 5;
    int lane = tid & 31;
    if (tid < NE) lcount[tid] = 0;
    __syncthreads();

    int b = blockIdx.x * 32 + warp;

    float raw[NE];
    float mx = -1e30f;
#pragma unroll
    for (int e = 0; e < NE; e++) { raw[e] = logits[b * NE + e]; mx = fmaxf(mx, raw[e]); }
    float sum = 0.f;
#pragma unroll
    for (int e = 0; e < NE; e++) { raw[e] = expf(raw[e] - mx); sum += raw[e]; }
    float inv = 1.f / sum;
    int m[NE];
#pragma unroll
    for (int e = 0; e < NE; e++) { raw[e] *= inv; m[e] = masks[b * NE + e]; }

    float w[NE]; float isum = 0.f;
#pragma unroll
    for (int e = 0; e < NE; e++) { w[e] = (m[e] == 1) ? 0.f : raw[e]; isum += w[e]; }
    float winv = 1.f / (isum + EPSF);

    float a[NE]; float srow = 0.f;
#pragma unroll
    for (int e = 0; e < NE; e++) {
        w[e] *= winv;
        a[e] = (m[e] == 1) ? raw[e] : 0.f;
        srow += a[e];
    }

    float v1 = -1.f, v2 = -1.f; int e1 = 0, e2 = 0;
#pragma unroll
    for (int e = 0; e < NE; e++) {
        if (a[e] > v1) { v2 = v1; e2 = e1; v1 = a[e]; e1 = e; }
        else if (a[e] > v2) { v2 = a[e]; e2 = e; }
    }
    float gs = 1.f / (v1 + v2 + EPSF);
    float g1 = v1 * gs, g2 = v2 * gs;

    if (lane == 0) {
#pragma unroll
        for (int e = 0; e < NE; e++) g_iw[b * NE + e] = w[e];
        g_gate[2 * b]     = g1;
        g_gate[2 * b + 1] = g2;
        if (g1 > 0.f) { int p = atomicAdd(&lcount[e1], 1); staging[e1][p] = 2 * b; }
        if (g2 > 0.f) { int p = atomicAdd(&lcount[e2], 1); staging[e2][p] = 2 * b + 1; }
        warpS[warp] = srow;
    }
    __syncthreads();
    if (tid < NE) lbase[tid] = atomicAdd(&g_count[tid], lcount[tid]);
    if (tid == 0) {
        float s = 0.f;
        for (int i = 0; i < 32; i++) s += warpS[i];
        g_partial[blockIdx.x] = s;
    }
    __syncthreads();
#pragma unroll
    for (int e = 0; e < NE; e++) {
        for (int i = tid; i < lcount[e]; i += blockDim.x)
            g_bucket[e * NB + lbase[e] + i] = staging[e][i];
    }
}

// ---------------------------------------------------------------------------
// Split X into bf16 hi/lo, pad K to 928 with zeros.
__global__ void split_x_kernel(const float* __restrict__ X) {
    size_t i = (size_t)blockIdx.x * blockDim.x + threadIdx.x;
    if (i >= (size_t)NB * KP) return;
    int b = (int)(i / KP), k = (int)(i % KP);
    float v = (k < DIN) ? X[(size_t)b * DIN + k] : 0.f;
    __nv_bfloat16 h = __float2bfloat16(v);
    g_Xhi[i] = h;
    g_Xlo[i] = __float2bfloat16(v - __bfloat162float(h));
}

// ---------------------------------------------------------------------------
// Transpose + split W[e][k][n] -> [e][n][kpad] bf16 hi/lo.
__global__ void split_w_kernel(const float* __restrict__ W) {
    __shared__ float tile[32][33];
    int e = blockIdx.z;
    int k0 = blockIdx.x * 32;
    int n0 = blockIdx.y * 32;
    int tx = threadIdx.x, ty = threadIdx.y;
#pragma unroll
    for (int i = 0; i < 4; i++) {
        int k = k0 + ty + i * 8;
        tile[ty + i * 8][tx] = (k < DIN) ? W[((size_t)e * DIN + k) * DM + n0 + tx] : 0.f;
    }
    __syncthreads();
#pragma unroll
    for (int i = 0; i < 4; i++) {
        int n = n0 + ty + i * 8;
        int kk = k0 + tx;
        if (kk < KP) {
            float v = tile[tx][ty + i * 8];
            __nv_bfloat16 h = __float2bfloat16(v);
            size_t idx = ((size_t)e * DM + n) * KP + kk;
            g_Whi[idx] = h;
            g_Wlo[idx] = __float2bfloat16(v - __bfloat162float(h));
        }
    }
}

// ---------------------------------------------------------------------------
// Tensor-core grouped GEMM: mma.sync bf16, 3-pass hi/lo split.
// CTA tile 128x128, super-stage BK=32, 3-stage pipeline, one barrier per 32-K,
// XOR-swizzled dense 32B rows (conflict-free LDSM + conflict-free STS).
extern __shared__ char sm_dyn[];

__global__ void __launch_bounds__(256, 2) gemm_kernel(
    const float* __restrict__ bias)
{
    int e   = blockIdx.z;
    int cnt = g_count[e];
    int rt0 = blockIdx.x * 128;
    if (rt0 >= cnt) return;
    int rows = cnt - rt0; if (rows > 128) rows = 128;
    int n0 = blockIdx.y * 128;

    __shared__ int   sEntry[128];
    __shared__ float sGate[128];
    __shared__ float sBias[128];

    int t = threadIdx.x;
    int wid = t >> 5, lane = t & 31;
    int wm = wid & 1, wn = wid >> 1;       // 2 x 4 warp grid

    if (t < 128) {
        int entry = 0; float g = 0.f;
        if (t < rows) { entry = g_bucket[e * NB + rt0 + t]; g = g_gate[entry]; }
        sEntry[t] = entry; sGate[t] = g;
        sBias[t]  = bias[e * DM + n0 + t];
    }
    __syncthreads();

    uint32_t dynb = smem_u32(sm_dyn);

    // per-thread cp.async sources: row = t>>1, chunk = t&1 (16B each)
    int lrow = t >> 1, lch = t & 1;
    const __nv_bfloat16* aHiSrc =
        g_Xhi + (size_t)(sEntry[lrow] >> 1) * KP + lch * 8;
    const __nv_bfloat16* aLoSrc =
        g_Xlo + (size_t)(sEntry[lrow] >> 1) * KP + lch * 8;
    const __nv_bfloat16* bHiSrc =
        g_Whi + ((size_t)e * DM + n0 + lrow) * KP + lch * 8;
    const __nv_bfloat16* bLoSrc =
        g_Wlo + ((size_t)e * DM + n0 + lrow) * KP + lch * 8;
    uint32_t smoff = swz(lrow, lch);       // swizzled 16B slot for this thread

    // issue one super-stage (2 sub-blocks, 8 cp16 per thread)
    auto issue_super = [&](int sup) {
        uint32_t sb = dynb + (sup % NSTG) * SSTAGE;
#pragma unroll
        for (int s = 0; s < 2; s++) {
            uint32_t ssb = sb + s * SUB;
            int ko = sup * 32 + s * 16;
            cp16(ssb + AHI + smoff, aHiSrc + ko);
            cp16(ssb + ALO + smoff, aLoSrc + ko);
            cp16(ssb + BHI + smoff, bHiSrc + ko);
            cp16(ssb + BLO + smoff, bLoSrc + ko);
        }
    };

    // prologue: supers 0 and 1 (one commit group each)
    issue_super(0); cp_commit();
    issue_super(1); cp_commit();

    float acc[4][4][4];
#pragma unroll
    for (int i = 0; i < 4; i++)
#pragma unroll
        for (int j = 0; j < 4; j++)
#pragma unroll
            for (int q = 0; q < 4; q++) acc[i][j][q] = 0.f;

    // fragment address offsets (swizzled; the tm/p +16-row steps leave the
    // swizzle bit (row>>2)&1 invariant, so the offsets stay additive)
    int l7 = lane & 7;
    int aRow = wm * 64 + l7 + ((lane >> 3) & 1) * 8;
    uint32_t aRowOff = swz(aRow, (lane >> 4) & 1);
    int bRow = wn * 32 + ((lane >> 4) & 1) * 8 + l7;
    uint32_t bRow4Off = swz(bRow, (lane >> 3) & 1);

    for (int i = 0; i < NSUP; i++) {
        cp_wait<1>();       // own group for super i done (newest may pend)
        __syncthreads();    // publish super i; all warps done reading super i-1

        // refill the stage freed at iter i-1 (safe: all warps past barrier)
        if (i + 2 < NSUP) issue_super(i + 2);
        cp_commit();

        uint32_t sb = dynb + (i % NSTG) * SSTAGE;
#pragma unroll
        for (int s = 0; s < 2; s++) {
            uint32_t ssb = sb + s * SUB;

            // B fragments: 4 ldm_x4 (hi/lo x two tn-pairs)
            uint32_t bh[4][2], blo[4][2];
#pragma unroll
            for (int p = 0; p < 2; p++) {
                uint32_t r4[4];
                uint32_t ba = ssb + BHI + bRow4Off + p * 16 * 32;
                ldm_x4(r4, ba);
                bh[2 * p][0] = r4[0]; bh[2 * p][1] = r4[1];
                bh[2 * p + 1][0] = r4[2]; bh[2 * p + 1][1] = r4[3];
                ldm_x4(r4, ba + (BLO - BHI));
                blo[2 * p][0] = r4[0]; blo[2 * p][1] = r4[1];
                blo[2 * p + 1][0] = r4[2]; blo[2 * p + 1][1] = r4[3];
            }

            // A fragments: double-buffered across tm
            uint32_t ah[2][4], al[2][4];
            {
                uint32_t aa = ssb + AHI + aRowOff;
                ldm_x4(ah[0], aa);
                ldm_x4(al[0], aa + (ALO - AHI));
            }
#pragma unroll
            for (int tm = 0; tm < 4; tm++) {
                int cur = tm & 1;
                if (tm < 3) {
                    uint32_t aa = ssb + AHI + aRowOff + (tm + 1) * 16 * 32;
                    ldm_x4(ah[cur ^ 1], aa);
                    ldm_x4(al[cur ^ 1], aa + (ALO - AHI));
                }
                // pass-major issue: consecutive MMAs -> independent accumulators
#pragma unroll
                for (int tn = 0; tn < 4; tn++)
                    MMA_BF16(acc[tm][tn], ah[cur], bh[tn]);
#pragma unroll
                for (int tn = 0; tn < 4; tn++)
                    MMA_BF16(acc[tm][tn], ah[cur], blo[tn]);
#pragma unroll
                for (int tn = 0; tn < 4; tn++)
                    MMA_BF16(acc[tm][tn], al[cur], bh[tn]);
            }
        }
    }

    // epilogue: bias + gate, write to scratch
    int rq = lane >> 2, cq = (lane & 3) * 2;
#pragma unroll
    for (int tm = 0; tm < 4; tm++) {
        int r0 = wm * 64 + tm * 16 + rq;
        int r1 = r0 + 8;
#pragma unroll
        for (int tn = 0; tn < 4; tn++) {
            int cl = wn * 32 + tn * 8 + cq;
            float b0 = sBias[cl], b1 = sBias[cl + 1];
            if (r0 < rows) {
                float g = sGate[r0];
                float2 o = make_float2(g * (acc[tm][tn][0] + b0),
                                       g * (acc[tm][tn][1] + b1));
                *(float2*)(g_scratch + (size_t)sEntry[r0] * DM + n0 + cl) = o;
            }
            if (r1 < rows) {
                float g = sGate[r1];
                float2 o = make_float2(g * (acc[tm][tn][2] + b0),
                                       g * (acc[tm][tn][3] + b1));
                *(float2*)(g_scratch + (size_t)sEntry[r1] * DM + n0 + cl) = o;
            }
        }
    }
}

// ---------------------------------------------------------------------------
__global__ void guide_kernel(float* __restrict__ out) {
    __shared__ float sm[512];
    int t = threadIdx.x;
    sm[t] = g_partial[t];
    __syncthreads();
    for (int s = 256; s > 0; s >>= 1) {
        if (t < s) sm[t] += sm[t + s];
        __syncthreads();
    }
    if (t == 0) {
        float sv = sm[0] / (float)NB;
        float d = 1.f - sv;
        out[OUT_GUIDE] = d * d;
    }
}

// ---------------------------------------------------------------------------
// Streaming selection-embedding: out_sel[b, s] = sum_e iw[b,e]*selemb[b,e,s].
__global__ void __launch_bounds__(256) selemb_kernel(
    const float* __restrict__ selemb,
    float*       __restrict__ out)
{
    int warp = (blockIdx.x * 256 + threadIdx.x) >> 5;
    int lane = threadIdx.x & 31;
    int b = warp;

    float w[NE];
#pragma unroll
    for (int e = 0; e < NE; e++) w[e] = g_iw[b * NE + e];

    const float4* base = (const float4*)(selemb + (size_t)b * NE * DSEL);
    float4 acc = make_float4(0.f, 0.f, 0.f, 0.f);
#pragma unroll
    for (int e = 0; e < NE; e++) {
        float4 v = base[e * (DSEL / 4) + lane];
        acc.x += w[e] * v.x; acc.y += w[e] * v.y;
        acc.z += w[e] * v.z; acc.w += w[e] * v.w;
    }
    float* dst = out + OUT_SEL + (size_t)b * DSEL + lane * 4;
    dst[0] = acc.x; dst[1] = acc.y; dst[2] = acc.z; dst[3] = acc.w;
}

// ---------------------------------------------------------------------------
// Combine slot0 + slot1, quantize to bf16, write f32. Also resets g_count
// for the next graph replay (runs after gemm consumed the counts).
__global__ void combine_kernel(float* __restrict__ out) {
    int idx = blockIdx.x * blockDim.x + threadIdx.x;
    if (blockIdx.x == 0 && threadIdx.x < NE) g_count[threadIdx.x] = 0;
    int b   = idx >> 7;
    int m4  = (idx & 127) << 2;
    float g1 = g_gate[2 * b], g2 = g_gate[2 * b + 1];
    float4 v = make_float4(0.f, 0.f, 0.f, 0.f);
    if (g1 > 0.f) {
        float4 s = *(const float4*)(g_scratch + (size_t)(2 * b) * DM + m4);
        v.x += s.x; v.y += s.y; v.z += s.z; v.w += s.w;
    }
    if (g2 > 0.f) {
        float4 s = *(const float4*)(g_scratch + (size_t)(2 * b + 1) * DM + m4);
        v.x += s.x; v.y += s.y; v.z += s.z; v.w += s.w;
    }
    float4 o;
    o.x = __bfloat162float(__float2bfloat16(v.x));
    o.y = __bfloat162float(__float2bfloat16(v.y));
    o.z = __bfloat162float(__float2bfloat16(v.z));
    o.w = __bfloat162float(__float2bfloat16(v.w));
    ((float4*)out)[idx] = o;
}

// ---------------------------------------------------------------------------
extern "C" void kernel_launch(void* const* d_in, const int* in_sizes, int n_in,
                              void* d_out, int out_size)
{
    const float* X      = (const float*)d_in[0];
    const float* logits = (const float*)d_in[1];
    const int*   masks  = (const int*)  d_in[2];
    const float* selemb = (const float*)d_in[3];
    const float* W      = (const float*)d_in[4];
    const float* bias   = (const float*)d_in[5];
    float* out = (float*)d_out;

    cudaFuncSetAttribute(gemm_kernel,
                         cudaFuncAttributeMaxDynamicSharedMemorySize, DYNSM);

    phaseA_kernel<<<NB / 32, 1024>>>(logits, masks);                       // 1
    split_x_kernel<<<(int)(((size_t)NB * KP + 255) / 256), 256>>>(X);      // 2
    dim3 wg(KP / 32, DM / 32, NE);
    split_w_kernel<<<wg, dim3(32, 8)>>>(W);                                // 3
    dim3 g(NB / 128, DM / 128, NE);
    gemm_kernel<<<g, 256, DYNSM>>>(bias);                                  // 4 (profiled)
    guide_kernel<<<1, 512>>>(out);                                         // 5
    selemb_kernel<<<NB / 8, 256>>>(selemb, out);                           // 6
    combine_kernel<<<(NB * DM / 4) / 256, 256>>>(out);                     // 7
}

// round 13
// speedup vs baseline: 1.3678x; 1.2699x over previous
#include <cuda_runtime.h>
#include <cuda_fp16.h>
#include <cuda_bf16.h>
#include <cstdint>

#define NB   16384
#define NE   8
#define DIN  900
#define DM   512
#define DSEL 128
#define EPSF 1e-9f

#define KP     928            // 58 * 16, zero-padded K
#define NSUP   29             // super k-steps of K=32
#define NSTG   4              // super-stage pipeline depth
#define SSTAGE 24576          // bytes per super-stage (2 subs x 3 arrays x 128 x 32B)
#define SUB    12288          // bytes per 16-K sub-block
#define A1OFF  0
#define A2OFF  4096
#define BOFF   8192
#define DYNSM  (NSTG * SSTAGE) // 98304

#define OUT_GUIDE (NB * DM)
#define OUT_SEL   (NB * DM + 1)

__device__ float g_scratch[(size_t)2 * NB * DM];     // gated per-(token,slot) outputs
__device__ int   g_bucket[NE * NB];
__device__ int   g_count[NE];                        // zero-init at load; combine resets
__device__ float g_gate[2 * NB];
__device__ float g_iw[NB * NE];                      // inactive-mixture weights
__device__ float g_partial[512];
__device__ __half g_Xh1[(size_t)NB * KP];            // X fp16 hi limb
__device__ __half g_Xh2[(size_t)NB * KP];            // X fp16 lo limb
__device__ __half g_Wh[(size_t)NE * DM * KP];        // W transposed [e][n][k], fp16

// ---------------------------------------------------------------------------
__device__ __forceinline__ uint32_t smem_u32(const void* p) {
    return (uint32_t)__cvta_generic_to_shared(p);
}
__device__ __forceinline__ void cp16(uint32_t s, const void* g) {
    asm volatile("cp.async.cg.shared.global [%0], [%1], 16;" :: "r"(s), "l"(g));
}
__device__ __forceinline__ void cp_commit() {
    asm volatile("cp.async.commit_group;" ::: "memory");
}
template <int N>
__device__ __forceinline__ void cp_wait() {
    asm volatile("cp.async.wait_group %0;" :: "n"(N) : "memory");
}
__device__ __forceinline__ void ldm_x4(uint32_t* r, uint32_t a) {
    asm volatile("ldmatrix.sync.aligned.m8n8.x4.shared.b16 {%0,%1,%2,%3}, [%4];"
                 : "=r"(r[0]), "=r"(r[1]), "=r"(r[2]), "=r"(r[3]) : "r"(a));
}
#define MMA_F16(acc, a, b) \
    asm volatile("mma.sync.aligned.m16n8k16.row.col.f32.f16.f16.f32 " \
        "{%0,%1,%2,%3}, {%4,%5,%6,%7}, {%8,%9}, {%0,%1,%2,%3};" \
        : "+f"((acc)[0]), "+f"((acc)[1]), "+f"((acc)[2]), "+f"((acc)[3]) \
        : "r"((a)[0]), "r"((a)[1]), "r"((a)[2]), "r"((a)[3]), \
          "r"((b)[0]), "r"((b)[1]))

// swizzled offset for (row, chunk16) in a 128x32B array: kills LDSM conflicts
__device__ __forceinline__ uint32_t swz(int row, int chunk) {
    return (uint32_t)(row * 32 + (chunk ^ ((row >> 2) & 1)) * 16);
}

// ---------------------------------------------------------------------------
// Phase A lite: softmax, gates, top-2, bucketing, guide partials.
__global__ void __launch_bounds__(1024) phaseA_kernel(
    const float* __restrict__ logits,
    const int*   __restrict__ masks)
{
    __shared__ int   lcount[NE];
    __shared__ int   lbase[NE];
    __shared__ int   staging[NE][32];
    __shared__ float warpS[32];

    int tid  = threadIdx.x;
    int warp = tid >> 5;
    int lane = tid & 31;
    if (tid < NE) lcount[tid] = 0;
    __syncthreads();

    int b = blockIdx.x * 32 + warp;

    float raw[NE];
    float mx = -1e30f;
#pragma unroll
    for (int e = 0; e < NE; e++) { raw[e] = logits[b * NE + e]; mx = fmaxf(mx, raw[e]); }
    float sum = 0.f;
#pragma unroll
    for (int e = 0; e < NE; e++) { raw[e] = expf(raw[e] - mx); sum += raw[e]; }
    float inv = 1.f / sum;
    int m[NE];
#pragma unroll
    for (int e = 0; e < NE; e++) { raw[e] *= inv; m[e] = masks[b * NE + e]; }

    float w[NE]; float isum = 0.f;
#pragma unroll
    for (int e = 0; e < NE; e++) { w[e] = (m[e] == 1) ? 0.f : raw[e]; isum += w[e]; }
    float winv = 1.f / (isum + EPSF);

    float a[NE]; float srow = 0.f;
#pragma unroll
    for (int e = 0; e < NE; e++) {
        w[e] *= winv;
        a[e] = (m[e] == 1) ? raw[e] : 0.f;
        srow += a[e];
    }

    float v1 = -1.f, v2 = -1.f; int e1 = 0, e2 = 0;
#pragma unroll
    for (int e = 0; e < NE; e++) {
        if (a[e] > v1) { v2 = v1; e2 = e1; v1 = a[e]; e1 = e; }
        else if (a[e] > v2) { v2 = a[e]; e2 = e; }
    }
    float gs = 1.f / (v1 + v2 + EPSF);
    float g1 = v1 * gs, g2 = v2 * gs;

    if (lane == 0) {
#pragma unroll
        for (int e = 0; e < NE; e++) g_iw[b * NE + e] = w[e];
        g_gate[2 * b]     = g1;
        g_gate[2 * b + 1] = g2;
        if (g1 > 0.f) { int p = atomicAdd(&lcount[e1], 1); staging[e1][p] = 2 * b; }
        if (g2 > 0.f) { int p = atomicAdd(&lcount[e2], 1); staging[e2][p] = 2 * b + 1; }
        warpS[warp] = srow;
    }
    __syncthreads();
    if (tid < NE) lbase[tid] = atomicAdd(&g_count[tid], lcount[tid]);
    if (tid == 0) {
        float s = 0.f;
        for (int i = 0; i < 32; i++) s += warpS[i];
        g_partial[blockIdx.x] = s;
    }
    __syncthreads();
#pragma unroll
    for (int e = 0; e < NE; e++) {
        for (int i = tid; i < lcount[e]; i += blockDim.x)
            g_bucket[e * NB + lbase[e] + i] = staging[e][i];
    }
}

// ---------------------------------------------------------------------------
// Split X into fp16 hi/lo limbs (x = x1 + x2, ~22 bits), pad K to 928.
__global__ void split_x_kernel(const float* __restrict__ X) {
    size_t i = (size_t)blockIdx.x * blockDim.x + threadIdx.x;
    if (i >= (size_t)NB * KP) return;
    int b = (int)(i / KP), k = (int)(i % KP);
    float v = (k < DIN) ? X[(size_t)b * DIN + k] : 0.f;
    __half h = __float2half(v);
    g_Xh1[i] = h;
    g_Xh2[i] = __float2half(v - __half2float(h));
}

// ---------------------------------------------------------------------------
// Transpose W[e][k][n] -> [e][n][kpad] single fp16 limb.
__global__ void split_w_kernel(const float* __restrict__ W) {
    __shared__ float tile[32][33];
    int e = blockIdx.z;
    int k0 = blockIdx.x * 32;
    int n0 = blockIdx.y * 32;
    int tx = threadIdx.x, ty = threadIdx.y;
#pragma unroll
    for (int i = 0; i < 4; i++) {
        int k = k0 + ty + i * 8;
        tile[ty + i * 8][tx] = (k < DIN) ? W[((size_t)e * DIN + k) * DM + n0 + tx] : 0.f;
    }
    __syncthreads();
#pragma unroll
    for (int i = 0; i < 4; i++) {
        int n = n0 + ty + i * 8;
        int kk = k0 + tx;
        if (kk < KP) {
            g_Wh[((size_t)e * DM + n) * KP + kk] = __float2half(tile[tx][ty + i * 8]);
        }
    }
}

// ---------------------------------------------------------------------------
// Tensor-core grouped GEMM: mma.sync fp16, 2-pass X-limb split (x1*w + x2*w).
// CTA tile 128x128, super-stage BK=32, 4-stage pipeline, one barrier per 32-K,
// XOR-swizzled dense 32B rows. 32 MMA + 10 LDSM per warp per 16-K sub-step.
extern __shared__ char sm_dyn[];

__global__ void __launch_bounds__(256, 2) gemm_kernel(
    const float* __restrict__ bias)
{
    int e   = blockIdx.z;
    int cnt = g_count[e];
    int rt0 = blockIdx.x * 128;
    if (rt0 >= cnt) return;
    int rows = cnt - rt0; if (rows > 128) rows = 128;
    int n0 = blockIdx.y * 128;

    __shared__ int   sEntry[128];
    __shared__ float sGate[128];
    __shared__ float sBias[128];

    int t = threadIdx.x;
    int wid = t >> 5, lane = t & 31;
    int wm = wid & 1, wn = wid >> 1;       // 2 x 4 warp grid

    if (t < 128) {
        int entry = 0; float g = 0.f;
        if (t < rows) { entry = g_bucket[e * NB + rt0 + t]; g = g_gate[entry]; }
        sEntry[t] = entry; sGate[t] = g;
        sBias[t]  = bias[e * DM + n0 + t];
    }
    __syncthreads();

    uint32_t dynb = smem_u32(sm_dyn);

    // per-thread cp.async sources: row = t>>1, chunk = t&1 (16B each)
    int lrow = t >> 1, lch = t & 1;
    const __half* a1Src = g_Xh1 + (size_t)(sEntry[lrow] >> 1) * KP + lch * 8;
    const __half* a2Src = g_Xh2 + (size_t)(sEntry[lrow] >> 1) * KP + lch * 8;
    const __half* bSrc  = g_Wh + ((size_t)e * DM + n0 + lrow) * KP + lch * 8;
    uint32_t smoff = swz(lrow, lch);       // swizzled 16B slot for this thread

    // issue one super-stage (2 sub-blocks, 6 cp16 per thread)
    auto issue_super = [&](int sup) {
        uint32_t sb = dynb + (sup % NSTG) * SSTAGE;
#pragma unroll
        for (int s = 0; s < 2; s++) {
            uint32_t ssb = sb + s * SUB;
            int ko = sup * 32 + s * 16;
            cp16(ssb + A1OFF + smoff, a1Src + ko);
            cp16(ssb + A2OFF + smoff, a2Src + ko);
            cp16(ssb + BOFF + smoff, bSrc + ko);
        }
    };

    // prologue: supers 0..2 (one commit group each)
    issue_super(0); cp_commit();
    issue_super(1); cp_commit();
    issue_super(2); cp_commit();

    float acc[4][4][4];
#pragma unroll
    for (int i = 0; i < 4; i++)
#pragma unroll
        for (int j = 0; j < 4; j++)
#pragma unroll
            for (int q = 0; q < 4; q++) acc[i][j][q] = 0.f;

    // fragment address offsets (swizzled; +16-row steps leave swizzle additive)
    int l7 = lane & 7;
    int aRow = wm * 64 + l7 + ((lane >> 3) & 1) * 8;
    uint32_t aRowOff = swz(aRow, (lane >> 4) & 1);
    int bRow = wn * 32 + ((lane >> 4) & 1) * 8 + l7;
    uint32_t bRow4Off = swz(bRow, (lane >> 3) & 1);

    for (int i = 0; i < NSUP; i++) {
        cp_wait<2>();       // super i's group done (2 newest may pend)
        __syncthreads();    // publish super i; all warps done reading super i-1

        // refill the stage freed at iter i-1 (safe: all warps past barrier)
        if (i + 3 < NSUP) issue_super(i + 3);
        cp_commit();

        uint32_t sb = dynb + (i % NSTG) * SSTAGE;
#pragma unroll
        for (int s = 0; s < 2; s++) {
            uint32_t ssb = sb + s * SUB;

            // B fragments: 2 ldm_x4 (two tn-pairs)
            uint32_t bh[4][2];
#pragma unroll
            for (int p = 0; p < 2; p++) {
                uint32_t r4[4];
                ldm_x4(r4, ssb + BOFF + bRow4Off + p * 16 * 32);
                bh[2 * p][0] = r4[0]; bh[2 * p][1] = r4[1];
                bh[2 * p + 1][0] = r4[2]; bh[2 * p + 1][1] = r4[3];
            }

            // A fragments (limb1 + limb2): double-buffered across tm
            uint32_t a1[2][4], a2[2][4];
            {
                uint32_t aa = ssb + A1OFF + aRowOff;
                ldm_x4(a1[0], aa);
                ldm_x4(a2[0], aa + (A2OFF - A1OFF));
            }
#pragma unroll
            for (int tm = 0; tm < 4; tm++) {
                int cur = tm & 1;
                if (tm < 3) {
                    uint32_t aa = ssb + A1OFF + aRowOff + (tm + 1) * 16 * 32;
                    ldm_x4(a1[cur ^ 1], aa);
                    ldm_x4(a2[cur ^ 1], aa + (A2OFF - A1OFF));
                }
                // pass-major issue: consecutive MMAs -> independent accumulators
#pragma unroll
                for (int tn = 0; tn < 4; tn++)
                    MMA_F16(acc[tm][tn], a1[cur], bh[tn]);
#pragma unroll
                for (int tn = 0; tn < 4; tn++)
                    MMA_F16(acc[tm][tn], a2[cur], bh[tn]);
            }
        }
    }

    // epilogue: bias + gate, write to scratch
    int rq = lane >> 2, cq = (lane & 3) * 2;
#pragma unroll
    for (int tm = 0; tm < 4; tm++) {
        int r0 = wm * 64 + tm * 16 + rq;
        int r1 = r0 + 8;
#pragma unroll
        for (int tn = 0; tn < 4; tn++) {
            int cl = wn * 32 + tn * 8 + cq;
            float b0 = sBias[cl], b1 = sBias[cl + 1];
            if (r0 < rows) {
                float g = sGate[r0];
                float2 o = make_float2(g * (acc[tm][tn][0] + b0),
                                       g * (acc[tm][tn][1] + b1));
                *(float2*)(g_scratch + (size_t)sEntry[r0] * DM + n0 + cl) = o;
            }
            if (r1 < rows) {
                float g = sGate[r1];
                float2 o = make_float2(g * (acc[tm][tn][2] + b0),
                                       g * (acc[tm][tn][3] + b1));
                *(float2*)(g_scratch + (size_t)sEntry[r1] * DM + n0 + cl) = o;
            }
        }
    }
}

// ---------------------------------------------------------------------------
__global__ void guide_kernel(float* __restrict__ out) {
    __shared__ float sm[512];
    int t = threadIdx.x;
    sm[t] = g_partial[t];
    __syncthreads();
    for (int s = 256; s > 0; s >>= 1) {
        if (t < s) sm[t] += sm[t + s];
        __syncthreads();
    }
    if (t == 0) {
        float sv = sm[0] / (float)NB;
        float d = 1.f - sv;
        out[OUT_GUIDE] = d * d;
    }
}

// ---------------------------------------------------------------------------
// Streaming selection-embedding: out_sel[b, s] = sum_e iw[b,e]*selemb[b,e,s].
__global__ void __launch_bounds__(256) selemb_kernel(
    const float* __restrict__ selemb,
    float*       __restrict__ out)
{
    int warp = (blockIdx.x * 256 + threadIdx.x) >> 5;
    int lane = threadIdx.x & 31;
    int b = warp;

    float w[NE];
#pragma unroll
    for (int e = 0; e < NE; e++) w[e] = g_iw[b * NE + e];

    const float4* base = (const float4*)(selemb + (size_t)b * NE * DSEL);
    float4 acc = make_float4(0.f, 0.f, 0.f, 0.f);
#pragma unroll
    for (int e = 0; e < NE; e++) {
        float4 v = base[e * (DSEL / 4) + lane];
        acc.x += w[e] * v.x; acc.y += w[e] * v.y;
        acc.z += w[e] * v.z; acc.w += w[e] * v.w;
    }
    float* dst = out + OUT_SEL + (size_t)b * DSEL + lane * 4;
    dst[0] = acc.x; dst[1] = acc.y; dst[2] = acc.z; dst[3] = acc.w;
}

// ---------------------------------------------------------------------------
// Combine slot0 + slot1, quantize to bf16, write f32. Also resets g_count
// for the next graph replay (runs after gemm consumed the counts).
__global__ void combine_kernel(float* __restrict__ out) {
    int idx = blockIdx.x * blockDim.x + threadIdx.x;
    if (blockIdx.x == 0 && threadIdx.x < NE) g_count[threadIdx.x] = 0;
    int b   = idx >> 7;
    int m4  = (idx & 127) << 2;
    float g1 = g_gate[2 * b], g2 = g_gate[2 * b + 1];
    float4 v = make_float4(0.f, 0.f, 0.f, 0.f);
    if (g1 > 0.f) {
        float4 s = *(const float4*)(g_scratch + (size_t)(2 * b) * DM + m4);
        v.x += s.x; v.y += s.y; v.z += s.z; v.w += s.w;
    }
    if (g2 > 0.f) {
        float4 s = *(const float4*)(g_scratch + (size_t)(2 * b + 1) * DM + m4);
        v.x += s.x; v.y += s.y; v.z += s.z; v.w += s.w;
    }
    float4 o;
    o.x = __bfloat162float(__float2bfloat16(v.x));
    o.y = __bfloat162float(__float2bfloat16(v.y));
    o.z = __bfloat162float(__float2bfloat16(v.z));
    o.w = __bfloat162float(__float2bfloat16(v.w));
    ((float4*)out)[idx] = o;
}

// ---------------------------------------------------------------------------
extern "C" void kernel_launch(void* const* d_in, const int* in_sizes, int n_in,
                              void* d_out, int out_size)
{
    const float* X      = (const float*)d_in[0];
    const float* logits = (const float*)d_in[1];
    const int*   masks  = (const int*)  d_in[2];
    const float* selemb = (const float*)d_in[3];
    const float* W      = (const float*)d_in[4];
    const float* bias   = (const float*)d_in[5];
    float* out = (float*)d_out;

    cudaFuncSetAttribute(gemm_kernel,
                         cudaFuncAttributeMaxDynamicSharedMemorySize, DYNSM);

    phaseA_kernel<<<NB / 32, 1024>>>(logits, masks);                       // 1
    split_x_kernel<<<(int)(((size_t)NB * KP + 255) / 256), 256>>>(X);      // 2
    dim3 wg(KP / 32, DM / 32, NE);
    split_w_kernel<<<wg, dim3(32, 8)>>>(W);                                // 3
    dim3 g(NB / 128, DM / 128, NE);
    gemm_kernel<<<g, 256, DYNSM>>>(bias);                                  // 4 (profiled)
    guide_kernel<<<1, 512>>>(out);                                         // 5
    selemb_kernel<<<NB / 8, 256>>>(selemb, out);                           // 6
    combine_kernel<<<(NB * DM / 4) / 256, 256>>>(out);                     // 7
}